// round 1
// baseline (speedup 1.0000x reference)
#include <cuda_runtime.h>
#include <math.h>

// ---------------- problem constants ----------------
#define NWIN 256          // num windows * batch
#define NTOK 256          // tokens per window
#define NC   384          // channels
#define NH   12           // heads
#define DH   32           // head dim
#define MROWS (NWIN*NTOK) // 65536
#define BHD (NTOK*DH)     // 8192 floats per (b,h) slice

// ---------------- scratch (device globals; no allocations allowed) ------
__device__ float g_q[(size_t)NWIN*NH*BHD];     // [b][h][n][d]
__device__ float g_k[(size_t)NWIN*NH*BHD];
__device__ float g_v[(size_t)NWIN*NH*BHD];
__device__ float g_ao[(size_t)MROWS*NC];       // attention output [b*n][h*32+d]
__device__ float g_bt[961*NH];                 // cpb bias table
__device__ float g_rpbT[(size_t)NH*NTOK*NTOK]; // 16*sigmoid(rpb), layout [h][j][qi]

// ================= CPB MLP: 2 -> 512 -> 12 per table entry ==============
__global__ void cpb_kernel(const float* __restrict__ table,
                           const float* __restrict__ w1,
                           const float* __restrict__ b1,
                           const float* __restrict__ w2)
{
    __shared__ float sh[512];
    const int e = blockIdx.x;         // 0..960
    const int t = threadIdx.x;        // 0..511
    const float c0 = table[e*2+0], c1 = table[e*2+1];
    float hid = fmaf(c0, w1[t*2+0], fmaf(c1, w1[t*2+1], b1[t]));
    sh[t] = fmaxf(hid, 0.f);
    __syncthreads();
    const int w = t >> 5, l = t & 31;
    if (w < NH) {
        float s = 0.f;
        #pragma unroll
        for (int i = 0; i < 16; i++)
            s = fmaf(sh[l + i*32], w2[w*512 + l + i*32], s);
        #pragma unroll
        for (int o = 16; o > 0; o >>= 1)
            s += __shfl_xor_sync(0xffffffffu, s, o);
        if (l == 0) g_bt[e*NH + w] = s;
    }
}

// ============ gather + 16*sigmoid into transposed layout [h][j][qi] =====
__global__ void gather_kernel(const int* __restrict__ rpi)
{
    const int qi = threadIdx.x;       // 0..255
    const int j  = blockIdx.x;        // 0..255
    const int idx = rpi[qi*NTOK + j];
    #pragma unroll
    for (int h = 0; h < NH; h++) {
        float bv = g_bt[idx*NH + h];
        float sg = 16.f / (1.f + __expf(-bv));
        g_rpbT[((size_t)h*NTOK + j)*NTOK + qi] = sg;  // coalesced on qi
    }
}

// ================= QKV GEMM: out[r][c] = x[r]·qkv_w[c] + bias ===========
// 128x128 tile, BK=16, 256 threads, 8x8 per thread. Epilogue scatters into
// g_q/g_k/g_v with q/v bias (k bias = 0). Each 128-col tile lies entirely
// inside one of q/k/v (1152 = 3*384, 384 % 128 == 0).
__global__ __launch_bounds__(256) void qkv_gemm_kernel(
    const float* __restrict__ A,   // x [65536,384]
    const float* __restrict__ W,   // qkv_w [1152,384]
    const float* __restrict__ qb,
    const float* __restrict__ vb)
{
    __shared__ float As[16][128];
    __shared__ float Bs[16][128];
    const int row0 = blockIdx.y * 128;
    const int col0 = blockIdx.x * 128;
    const int t = threadIdx.x;
    const int tx = t & 15, ty = t >> 4;

    float acc[8][8];
    #pragma unroll
    for (int i = 0; i < 8; i++)
        #pragma unroll
        for (int j = 0; j < 8; j++) acc[i][j] = 0.f;

    for (int k0 = 0; k0 < NC; k0 += 16) {
        #pragma unroll
        for (int i = 0; i < 2; i++) {
            int f = t + i*256;
            int r = f >> 2, kq = (f & 3) << 2;
            float4 va = *(const float4*)(A + (size_t)(row0 + r)*NC + k0 + kq);
            As[kq+0][r] = va.x; As[kq+1][r] = va.y; As[kq+2][r] = va.z; As[kq+3][r] = va.w;
            float4 vb4 = *(const float4*)(W + (size_t)(col0 + r)*NC + k0 + kq);
            Bs[kq+0][r] = vb4.x; Bs[kq+1][r] = vb4.y; Bs[kq+2][r] = vb4.z; Bs[kq+3][r] = vb4.w;
        }
        __syncthreads();
        #pragma unroll
        for (int kk = 0; kk < 16; kk++) {
            float4 a0 = *(const float4*)&As[kk][ty*8];
            float4 a1 = *(const float4*)&As[kk][ty*8+4];
            float4 b0 = *(const float4*)&Bs[kk][tx*8];
            float4 b1 = *(const float4*)&Bs[kk][tx*8+4];
            float a[8] = {a0.x,a0.y,a0.z,a0.w,a1.x,a1.y,a1.z,a1.w};
            float b[8] = {b0.x,b0.y,b0.z,b0.w,b1.x,b1.y,b1.z,b1.w};
            #pragma unroll
            for (int i = 0; i < 8; i++)
                #pragma unroll
                for (int j = 0; j < 8; j++)
                    acc[i][j] = fmaf(a[i], b[j], acc[i][j]);
        }
        __syncthreads();
    }

    // epilogue: scatter to q/k/v with bias
    const int which = col0 / NC;        // 0=q,1=k,2=v
    const int cbase = col0 % NC;        // 0,128,256
    const int cw0 = cbase + tx*8;       // within [0,384)
    const int hh = cw0 >> 5;
    const int d0 = cw0 & 31;
    float bias[8];
    #pragma unroll
    for (int j = 0; j < 8; j++)
        bias[j] = (which == 0) ? qb[cw0+j] : (which == 2) ? vb[cw0+j] : 0.f;
    float* dst = (which == 0) ? g_q : (which == 1) ? g_k : g_v;
    #pragma unroll
    for (int i = 0; i < 8; i++) {
        int r = row0 + ty*8 + i;
        int b = r >> 8, n = r & 255;
        float* p = dst + ((((size_t)b*NH + hh)*NTOK) + n)*DH + d0;
        float4 o0 = make_float4(acc[i][0]+bias[0], acc[i][1]+bias[1],
                                acc[i][2]+bias[2], acc[i][3]+bias[3]);
        float4 o1 = make_float4(acc[i][4]+bias[4], acc[i][5]+bias[5],
                                acc[i][6]+bias[6], acc[i][7]+bias[7]);
        *(float4*)p = o0; *(float4*)(p+4) = o1;
    }
}

// ================= Proj GEMM: d_out[r][c] = g_ao[r]·proj_w[c] + b =======
__global__ __launch_bounds__(256) void proj_gemm_kernel(
    const float* __restrict__ W,   // proj_w [384,384]
    const float* __restrict__ pb,
    float* __restrict__ out)
{
    __shared__ float As[16][128];
    __shared__ float Bs[16][128];
    const int row0 = blockIdx.y * 128;
    const int col0 = blockIdx.x * 128;
    const int t = threadIdx.x;
    const int tx = t & 15, ty = t >> 4;

    float acc[8][8];
    #pragma unroll
    for (int i = 0; i < 8; i++)
        #pragma unroll
        for (int j = 0; j < 8; j++) acc[i][j] = 0.f;

    for (int k0 = 0; k0 < NC; k0 += 16) {
        #pragma unroll
        for (int i = 0; i < 2; i++) {
            int f = t + i*256;
            int r = f >> 2, kq = (f & 3) << 2;
            float4 va = *(const float4*)(g_ao + (size_t)(row0 + r)*NC + k0 + kq);
            As[kq+0][r] = va.x; As[kq+1][r] = va.y; As[kq+2][r] = va.z; As[kq+3][r] = va.w;
            float4 vb4 = *(const float4*)(W + (size_t)(col0 + r)*NC + k0 + kq);
            Bs[kq+0][r] = vb4.x; Bs[kq+1][r] = vb4.y; Bs[kq+2][r] = vb4.z; Bs[kq+3][r] = vb4.w;
        }
        __syncthreads();
        #pragma unroll
        for (int kk = 0; kk < 16; kk++) {
            float4 a0 = *(const float4*)&As[kk][ty*8];
            float4 a1 = *(const float4*)&As[kk][ty*8+4];
            float4 b0 = *(const float4*)&Bs[kk][tx*8];
            float4 b1 = *(const float4*)&Bs[kk][tx*8+4];
            float a[8] = {a0.x,a0.y,a0.z,a0.w,a1.x,a1.y,a1.z,a1.w};
            float b[8] = {b0.x,b0.y,b0.z,b0.w,b1.x,b1.y,b1.z,b1.w};
            #pragma unroll
            for (int i = 0; i < 8; i++)
                #pragma unroll
                for (int j = 0; j < 8; j++)
                    acc[i][j] = fmaf(a[i], b[j], acc[i][j]);
        }
        __syncthreads();
    }

    float bias[8];
    #pragma unroll
    for (int j = 0; j < 8; j++) bias[j] = pb[col0 + tx*8 + j];
    #pragma unroll
    for (int i = 0; i < 8; i++) {
        int r = row0 + ty*8 + i;
        float* p = out + (size_t)r*NC + col0 + tx*8;
        float4 o0 = make_float4(acc[i][0]+bias[0], acc[i][1]+bias[1],
                                acc[i][2]+bias[2], acc[i][3]+bias[3]);
        float4 o1 = make_float4(acc[i][4]+bias[4], acc[i][5]+bias[5],
                                acc[i][6]+bias[6], acc[i][7]+bias[7]);
        *(float4*)p = o0; *(float4*)(p+4) = o1;
    }
}

// ================= Attention: one block per (window, head) ==============
// K,V in smem (raw), k inverse-norms in smem, q normalized+scaled in regs.
// Two-pass softmax (pass1 max, pass2 exp+accumulate) for stability.
__global__ __launch_bounds__(256) void attn_kernel(const float* __restrict__ logit_scale)
{
    extern __shared__ float sm[];
    float* Ks   = sm;             // 8192
    float* Vs   = sm + BHD;       // 8192
    float* kinv = sm + 2*BHD;     // 256

    const int bh = blockIdx.x;    // b*12 + h
    const int h  = bh % NH;
    const int b  = bh / NH;
    const int t  = threadIdx.x;   // query row

    const float* Kg = g_k + (size_t)bh*BHD;
    const float* Vg = g_v + (size_t)bh*BHD;
    #pragma unroll
    for (int i = t; i < BHD/4; i += 256) {
        ((float4*)Ks)[i] = ((const float4*)Kg)[i];
        ((float4*)Vs)[i] = ((const float4*)Vg)[i];
    }
    __syncthreads();

    // K row inverse norms via warp transposed reduction (conflict-free)
    {
        const int w = t >> 5, l = t & 31;
        for (int rr = 0; rr < 32; rr++) {
            int r = (w << 5) + rr;
            float x = Ks[r*DH + l];
            float s = x * x;
            #pragma unroll
            for (int o = 16; o > 0; o >>= 1)
                s += __shfl_xor_sync(0xffffffffu, s, o);
            if (l == 0) kinv[r] = 1.f / fmaxf(sqrtf(s), 1e-12f);
        }
    }

    // q: load, normalize, fold in clamped logit scale
    float q[DH];
    {
        const float* Qg = g_q + (size_t)bh*BHD + t*DH;
        float s = 0.f;
        #pragma unroll
        for (int d = 0; d < DH; d += 4) {
            float4 v4 = *(const float4*)(Qg + d);
            q[d] = v4.x; q[d+1] = v4.y; q[d+2] = v4.z; q[d+3] = v4.w;
        }
        #pragma unroll
        for (int d = 0; d < DH; d++) s = fmaf(q[d], q[d], s);
        float sc = __expf(fminf(logit_scale[h], 4.6051702f)); // ln(100)
        float f  = sc / fmaxf(sqrtf(s), 1e-12f);
        #pragma unroll
        for (int d = 0; d < DH; d++) q[d] *= f;
    }
    __syncthreads();

    const float* rp = g_rpbT + (size_t)h*(NTOK*NTOK) + t; // [j*256 + qi]

    // pass 1: row max
    float m = -1e30f;
    #pragma unroll 4
    for (int j = 0; j < NTOK; j++) {
        const float4* kr = (const float4*)(Ks + j*DH);
        float s = 0.f;
        #pragma unroll
        for (int dd = 0; dd < 8; dd++) {
            float4 kv = kr[dd];
            s = fmaf(q[4*dd+0], kv.x, s);
            s = fmaf(q[4*dd+1], kv.y, s);
            s = fmaf(q[4*dd+2], kv.z, s);
            s = fmaf(q[4*dd+3], kv.w, s);
        }
        s = fmaf(s, kinv[j], rp[j*NTOK]);
        m = fmaxf(m, s);
    }

    // pass 2: exp + accumulate
    float l = 0.f;
    float acc[DH];
    #pragma unroll
    for (int d = 0; d < DH; d++) acc[d] = 0.f;
    #pragma unroll 2
    for (int j = 0; j < NTOK; j++) {
        const float4* kr = (const float4*)(Ks + j*DH);
        float s = 0.f;
        #pragma unroll
        for (int dd = 0; dd < 8; dd++) {
            float4 kv = kr[dd];
            s = fmaf(q[4*dd+0], kv.x, s);
            s = fmaf(q[4*dd+1], kv.y, s);
            s = fmaf(q[4*dd+2], kv.z, s);
            s = fmaf(q[4*dd+3], kv.w, s);
        }
        s = fmaf(s, kinv[j], rp[j*NTOK]);
        float p = __expf(s - m);
        l += p;
        const float4* vr = (const float4*)(Vs + j*DH);
        #pragma unroll
        for (int dd = 0; dd < 8; dd++) {
            float4 vv = vr[dd];
            acc[4*dd+0] = fmaf(p, vv.x, acc[4*dd+0]);
            acc[4*dd+1] = fmaf(p, vv.y, acc[4*dd+1]);
            acc[4*dd+2] = fmaf(p, vv.z, acc[4*dd+2]);
            acc[4*dd+3] = fmaf(p, vv.w, acc[4*dd+3]);
        }
    }

    const float inv = 1.f / l;
    float* o = g_ao + (size_t)(b*NTOK + t)*NC + h*DH;
    #pragma unroll
    for (int d = 0; d < DH; d += 4) {
        float4 v4 = make_float4(acc[d]*inv, acc[d+1]*inv, acc[d+2]*inv, acc[d+3]*inv);
        *(float4*)(o + d) = v4;
    }
}

// =========================== launcher ====================================
extern "C" void kernel_launch(void* const* d_in, const int* in_sizes, int n_in,
                              void* d_out, int out_size)
{
    const float* x      = (const float*)d_in[0];
    const float* qkv_w  = (const float*)d_in[1];
    const float* q_bias = (const float*)d_in[2];
    const float* v_bias = (const float*)d_in[3];
    const float* lscale = (const float*)d_in[4];
    const float* cpb_w1 = (const float*)d_in[5];
    const float* cpb_b1 = (const float*)d_in[6];
    const float* cpb_w2 = (const float*)d_in[7];
    const float* proj_w = (const float*)d_in[8];
    const float* proj_b = (const float*)d_in[9];
    const float* rtab   = (const float*)d_in[10];
    const int*   rpi    = (const int*)d_in[11];
    float* out = (float*)d_out;

    const int attn_smem = (2*BHD + NTOK) * (int)sizeof(float); // 66560 B
    cudaFuncSetAttribute(attn_kernel, cudaFuncAttributeMaxDynamicSharedMemorySize, attn_smem);

    cpb_kernel<<<961, 512>>>(rtab, cpb_w1, cpb_b1, cpb_w2);
    gather_kernel<<<NTOK, NTOK>>>(rpi);

    dim3 gq(1152/128, MROWS/128);
    qkv_gemm_kernel<<<gq, 256>>>(x, qkv_w, q_bias, v_bias);

    attn_kernel<<<NWIN*NH, 256, attn_smem>>>(lscale);

    dim3 gp(NC/128, MROWS/128);
    proj_gemm_kernel<<<gp, 256>>>(proj_w, proj_b, out);
}

// round 2
// speedup vs baseline: 1.2632x; 1.2632x over previous
#include <cuda_runtime.h>
#include <math.h>

// ---------------- problem constants ----------------
#define NWIN 256
#define NTOK 256
#define NC   384
#define NH   12
#define DH   32
#define MROWS (NWIN*NTOK)
#define BHD (NTOK*DH)

typedef unsigned long long u64;

// ---------------- packed f32x2 helpers (sm_10x FFMA2 path) -------------
__device__ __forceinline__ u64 pk2(float x, float y){ u64 d; asm("mov.b64 %0,{%1,%2};":"=l"(d):"f"(x),"f"(y)); return d; }
__device__ __forceinline__ u64 dup2(float x){ u64 d; asm("mov.b64 %0,{%1,%1};":"=l"(d):"f"(x)); return d; }
__device__ __forceinline__ float2 up2(u64 d){ float2 r; asm("mov.b64 {%0,%1},%2;":"=f"(r.x),"=f"(r.y):"l"(d)); return r; }
__device__ __forceinline__ void fma2(u64& d, u64 a, u64 b){ asm("fma.rn.f32x2 %0,%1,%2,%0;":"+l"(d):"l"(a),"l"(b)); }

union F4U { float4 f; u64 u[2]; };

// ---------------- scratch ----------------
__device__ float g_q[(size_t)NWIN*NH*BHD];
__device__ float g_k[(size_t)NWIN*NH*BHD];
__device__ float g_v[(size_t)NWIN*NH*BHD];
__device__ float g_ao[(size_t)MROWS*NC];
__device__ float g_bt[961*NH];
__device__ float g_rpbT[(size_t)NH*NTOK*NTOK];   // [h][j][qi]

// ================= CPB MLP ==============
__global__ void cpb_kernel(const float* __restrict__ table,
                           const float* __restrict__ w1,
                           const float* __restrict__ b1,
                           const float* __restrict__ w2)
{
    __shared__ float sh[512];
    const int e = blockIdx.x;
    const int t = threadIdx.x;
    const float c0 = table[e*2+0], c1 = table[e*2+1];
    float hid = fmaf(c0, w1[t*2+0], fmaf(c1, w1[t*2+1], b1[t]));
    sh[t] = fmaxf(hid, 0.f);
    __syncthreads();
    const int w = t >> 5, l = t & 31;
    if (w < NH) {
        float s = 0.f;
        #pragma unroll
        for (int i = 0; i < 16; i++)
            s = fmaf(sh[l + i*32], w2[w*512 + l + i*32], s);
        #pragma unroll
        for (int o = 16; o > 0; o >>= 1)
            s += __shfl_xor_sync(0xffffffffu, s, o);
        if (l == 0) g_bt[e*NH + w] = s;
    }
}

// ============ gather + 16*sigmoid → [h][j][qi] =====
__global__ void gather_kernel(const int* __restrict__ rpi)
{
    const int qi = threadIdx.x;
    const int j  = blockIdx.x;
    const int idx = rpi[qi*NTOK + j];
    #pragma unroll
    for (int h = 0; h < NH; h++) {
        float bv = g_bt[idx*NH + h];
        float sg = 16.f / (1.f + __expf(-bv));
        g_rpbT[((size_t)h*NTOK + j)*NTOK + qi] = sg;
    }
}

// ================= QKV GEMM (f32x2) ===========
// 128x128x32 tiles; thread tile rows {ty*4, 64+ty*4}+0..3, cols {tx*4, 64+tx*4}+0..3
__global__ __launch_bounds__(256, 2) void qkv_gemm_kernel(
    const float* __restrict__ A,
    const float* __restrict__ W,
    const float* __restrict__ qb,
    const float* __restrict__ vb)
{
    __shared__ float As[32][132];
    __shared__ float Bs[32][132];
    const int row0 = blockIdx.y * 128;
    const int col0 = blockIdx.x * 128;
    const int t = threadIdx.x;
    const int tx = t & 15, ty = t >> 4;

    u64 acc[8][4];
    #pragma unroll
    for (int i = 0; i < 8; i++)
        #pragma unroll
        for (int j = 0; j < 4; j++) acc[i][j] = 0ull;

    for (int k0 = 0; k0 < NC; k0 += 32) {
        #pragma unroll
        for (int i = 0; i < 4; i++) {
            int f = t + i*256;
            int r = f >> 3, kq = (f & 7) << 2;
            float4 va = *(const float4*)(A + (size_t)(row0 + r)*NC + k0 + kq);
            As[kq+0][r] = va.x; As[kq+1][r] = va.y; As[kq+2][r] = va.z; As[kq+3][r] = va.w;
            float4 wb = *(const float4*)(W + (size_t)(col0 + r)*NC + k0 + kq);
            Bs[kq+0][r] = wb.x; Bs[kq+1][r] = wb.y; Bs[kq+2][r] = wb.z; Bs[kq+3][r] = wb.w;
        }
        __syncthreads();
        #pragma unroll 8
        for (int kk = 0; kk < 32; kk++) {
            float4 a0 = *(const float4*)&As[kk][ty*4];
            float4 a1 = *(const float4*)&As[kk][64 + ty*4];
            F4U b0, b1;
            b0.f = *(const float4*)&Bs[kk][tx*4];
            b1.f = *(const float4*)&Bs[kk][64 + tx*4];
            u64 a2[8] = {dup2(a0.x),dup2(a0.y),dup2(a0.z),dup2(a0.w),
                         dup2(a1.x),dup2(a1.y),dup2(a1.z),dup2(a1.w)};
            u64 b2[4] = {b0.u[0], b0.u[1], b1.u[0], b1.u[1]};
            #pragma unroll
            for (int i = 0; i < 8; i++)
                #pragma unroll
                for (int jp = 0; jp < 4; jp++)
                    fma2(acc[i][jp], a2[i], b2[jp]);
        }
        __syncthreads();
    }

    // epilogue: scatter to q/k/v with bias
    #pragma unroll
    for (int g = 0; g < 2; g++) {
        const int cglob = col0 + g*64 + tx*4;
        const int which = cglob / NC;
        const int cw = cglob % NC;
        const int hh = cw >> 5;
        const int d0 = cw & 31;
        float bias[4];
        #pragma unroll
        for (int j = 0; j < 4; j++)
            bias[j] = (which == 0) ? qb[cw+j] : (which == 2) ? vb[cw+j] : 0.f;
        float* dst = (which == 0) ? g_q : (which == 1) ? g_k : g_v;
        #pragma unroll
        for (int i = 0; i < 8; i++) {
            int r = row0 + (i>>2)*64 + ty*4 + (i&3);
            int b = r >> 8, n = r & 255;
            float2 p0 = up2(acc[i][g*2+0]);
            float2 p1 = up2(acc[i][g*2+1]);
            float* p = dst + ((((size_t)b*NH + hh)*NTOK) + n)*DH + d0;
            *(float4*)p = make_float4(p0.x+bias[0], p0.y+bias[1], p1.x+bias[2], p1.y+bias[3]);
        }
    }
}

// ================= Proj GEMM (f32x2) =======
__global__ __launch_bounds__(256, 2) void proj_gemm_kernel(
    const float* __restrict__ W,
    const float* __restrict__ pb,
    float* __restrict__ out)
{
    __shared__ float As[32][132];
    __shared__ float Bs[32][132];
    const int row0 = blockIdx.y * 128;
    const int col0 = blockIdx.x * 128;
    const int t = threadIdx.x;
    const int tx = t & 15, ty = t >> 4;

    u64 acc[8][4];
    #pragma unroll
    for (int i = 0; i < 8; i++)
        #pragma unroll
        for (int j = 0; j < 4; j++) acc[i][j] = 0ull;

    for (int k0 = 0; k0 < NC; k0 += 32) {
        #pragma unroll
        for (int i = 0; i < 4; i++) {
            int f = t + i*256;
            int r = f >> 3, kq = (f & 7) << 2;
            float4 va = *(const float4*)(g_ao + (size_t)(row0 + r)*NC + k0 + kq);
            As[kq+0][r] = va.x; As[kq+1][r] = va.y; As[kq+2][r] = va.z; As[kq+3][r] = va.w;
            float4 wb = *(const float4*)(W + (size_t)(col0 + r)*NC + k0 + kq);
            Bs[kq+0][r] = wb.x; Bs[kq+1][r] = wb.y; Bs[kq+2][r] = wb.z; Bs[kq+3][r] = wb.w;
        }
        __syncthreads();
        #pragma unroll 8
        for (int kk = 0; kk < 32; kk++) {
            float4 a0 = *(const float4*)&As[kk][ty*4];
            float4 a1 = *(const float4*)&As[kk][64 + ty*4];
            F4U b0, b1;
            b0.f = *(const float4*)&Bs[kk][tx*4];
            b1.f = *(const float4*)&Bs[kk][64 + tx*4];
            u64 a2[8] = {dup2(a0.x),dup2(a0.y),dup2(a0.z),dup2(a0.w),
                         dup2(a1.x),dup2(a1.y),dup2(a1.z),dup2(a1.w)};
            u64 b2[4] = {b0.u[0], b0.u[1], b1.u[0], b1.u[1]};
            #pragma unroll
            for (int i = 0; i < 8; i++)
                #pragma unroll
                for (int jp = 0; jp < 4; jp++)
                    fma2(acc[i][jp], a2[i], b2[jp]);
        }
        __syncthreads();
    }

    #pragma unroll
    for (int g = 0; g < 2; g++) {
        const int cglob = col0 + g*64 + tx*4;
        float bias[4];
        #pragma unroll
        for (int j = 0; j < 4; j++) bias[j] = pb[cglob + j];
        #pragma unroll
        for (int i = 0; i < 8; i++) {
            int r = row0 + (i>>2)*64 + ty*4 + (i&3);
            float2 p0 = up2(acc[i][g*2+0]);
            float2 p1 = up2(acc[i][g*2+1]);
            float* p = out + (size_t)r*NC + cglob;
            *(float4*)p = make_float4(p0.x+bias[0], p0.y+bias[1], p1.x+bias[2], p1.y+bias[3]);
        }
    }
}

// ================= Attention (single-pass, f32x2) ==============
// Score bound: qhat.khat in [-1,1], scale sc = exp(min(ls,ln100)), rpb in (0,16)
// -> s <= sc + 16 = M. Use fixed shift M; no max pass needed.
__global__ __launch_bounds__(256, 2) void attn_kernel(const float* __restrict__ logit_scale)
{
    extern __shared__ float sm[];
    float* Ks = sm;          // 8192 floats (L2-normalized in place)
    float* Vs = sm + BHD;    // 8192 floats

    const int bh = blockIdx.x;
    const int h  = bh % NH;
    const int b  = bh / NH;
    const int t  = threadIdx.x;

    const float* Kg = g_k + (size_t)bh*BHD;
    const float* Vg = g_v + (size_t)bh*BHD;
    #pragma unroll
    for (int i = t; i < BHD/4; i += 256) {
        ((float4*)Ks)[i] = ((const float4*)Kg)[i];
        ((float4*)Vs)[i] = ((const float4*)Vg)[i];
    }
    __syncthreads();

    // normalize K rows in place (transposed warp access: conflict-free)
    {
        const int w = t >> 5, l = t & 31;
        #pragma unroll 4
        for (int rr = 0; rr < 32; rr++) {
            int r = (w << 5) + rr;
            float x = Ks[r*DH + l];
            float s = x * x;
            #pragma unroll
            for (int o = 16; o > 0; o >>= 1)
                s += __shfl_xor_sync(0xffffffffu, s, o);
            float inv = 1.f / fmaxf(sqrtf(s), 1e-12f);
            Ks[r*DH + l] = x * inv;
        }
    }

    // q: load, normalize, fold clamped logit scale; pack to f32x2
    const float sc = __expf(fminf(logit_scale[h], 4.6051702f));
    const float M  = sc + 16.f;
    u64 q2[16];
    {
        const float* Qg = g_q + (size_t)bh*BHD + t*DH;
        float q[DH];
        float s = 0.f;
        #pragma unroll
        for (int d = 0; d < DH; d += 4) {
            float4 v4 = *(const float4*)(Qg + d);
            q[d] = v4.x; q[d+1] = v4.y; q[d+2] = v4.z; q[d+3] = v4.w;
        }
        #pragma unroll
        for (int d = 0; d < DH; d++) s = fmaf(q[d], q[d], s);
        float f = sc / fmaxf(sqrtf(s), 1e-12f);
        #pragma unroll
        for (int i = 0; i < 16; i++) q2[i] = pk2(q[2*i]*f, q[2*i+1]*f);
    }
    __syncthreads();

    const float* rp = g_rpbT + (size_t)h*(NTOK*NTOK) + t;
    const u64* Kp = (const u64*)Ks;
    const u64* Vp = (const u64*)Vs;

    float l = 0.f;
    u64 acc2[16];
    #pragma unroll
    for (int i = 0; i < 16; i++) acc2[i] = 0ull;

    #pragma unroll 2
    for (int j = 0; j < NTOK; j++) {
        const u64* kr = Kp + j*16;
        u64 sa = 0ull, sb = 0ull;
        #pragma unroll
        for (int i = 0; i < 8; i++) {
            fma2(sa, q2[2*i+0], kr[2*i+0]);
            fma2(sb, q2[2*i+1], kr[2*i+1]);
        }
        float2 ua = up2(sa), ub = up2(sb);
        float s = (ua.x + ub.x) + (ua.y + ub.y) + rp[j*NTOK];
        float p = __expf(s - M);
        l += p;
        u64 p2 = dup2(p);
        const u64* vr = Vp + j*16;
        #pragma unroll
        for (int i = 0; i < 16; i++)
            fma2(acc2[i], p2, vr[i]);
    }

    const float inv = 1.f / l;
    float* o = g_ao + (size_t)(b*NTOK + t)*NC + h*DH;
    #pragma unroll
    for (int i = 0; i < 16; i += 2) {
        float2 x = up2(acc2[i]), y = up2(acc2[i+1]);
        *(float4*)(o + i*2) = make_float4(x.x*inv, x.y*inv, y.x*inv, y.y*inv);
    }
}

// =========================== launcher ====================================
extern "C" void kernel_launch(void* const* d_in, const int* in_sizes, int n_in,
                              void* d_out, int out_size)
{
    const float* x      = (const float*)d_in[0];
    const float* qkv_w  = (const float*)d_in[1];
    const float* q_bias = (const float*)d_in[2];
    const float* v_bias = (const float*)d_in[3];
    const float* lscale = (const float*)d_in[4];
    const float* cpb_w1 = (const float*)d_in[5];
    const float* cpb_b1 = (const float*)d_in[6];
    const float* cpb_w2 = (const float*)d_in[7];
    const float* proj_w = (const float*)d_in[8];
    const float* proj_b = (const float*)d_in[9];
    const float* rtab   = (const float*)d_in[10];
    const int*   rpi    = (const int*)d_in[11];
    float* out = (float*)d_out;

    const int attn_smem = 2*BHD*(int)sizeof(float); // 65536 B
    cudaFuncSetAttribute(attn_kernel, cudaFuncAttributeMaxDynamicSharedMemorySize, attn_smem);

    cpb_kernel<<<961, 512>>>(rtab, cpb_w1, cpb_b1, cpb_w2);
    gather_kernel<<<NTOK, NTOK>>>(rpi);

    dim3 gq(1152/128, MROWS/128);
    qkv_gemm_kernel<<<gq, 256>>>(x, qkv_w, q_bias, v_bias);

    attn_kernel<<<NWIN*NH, 256, attn_smem>>>(lscale);

    dim3 gp(NC/128, MROWS/128);
    proj_gemm_kernel<<<gp, 256>>>(proj_w, proj_b, out);
}